// round 1
// baseline (speedup 1.0000x reference)
#include <cuda_runtime.h>
#include <cuda_bf16.h>
#include <cstdint>

// Problem constants (from reference): eeg_input [16, 32, 1000, 64] fp32
//   B*W = 512 batches, T = 1000, C = 64, PATCH = 200, nt = 5
// patches output for batch bw is the 64x1000 transpose of the 1000x64 input slab:
//   out[bw][c*1000 + t] = in[bw][t*64 + c]
// Index vectors (length C*nt = 320): channel = i/5, time = i%5.

#define N_BW   512
#define T_DIM  1000
#define C_DIM  64
#define TILE   32
#define PATCH_ELEMS (N_BW * T_DIM * C_DIM)   // 32,768,000 floats

__global__ __launch_bounds__(256) void labram_transpose_kernel(
    const float* __restrict__ in, float* __restrict__ out)
{
    __shared__ float tile[TILE][TILE + 1];

    const int bw    = blockIdx.z;
    const int tBase = blockIdx.y * TILE;
    const int cBase = blockIdx.x * TILE;

    const float* __restrict__ inp  = in  + (size_t)bw * (T_DIM * C_DIM);
    float*       __restrict__ outp = out + (size_t)bw * (T_DIM * C_DIM);

    const int tx = threadIdx.x;   // 0..31
    const int ty = threadIdx.y;   // 0..7

    // Load 32 (t) x 32 (c) tile, coalesced on c (innermost input dim).
    #pragma unroll
    for (int j = 0; j < 4; ++j) {
        const int t = tBase + ty + j * 8;
        if (t < T_DIM) {
            tile[ty + j * 8][tx] = inp[t * C_DIM + cBase + tx];
        }
    }
    __syncthreads();

    // Store transposed, coalesced on t (innermost output dim).
    const int t = tBase + tx;
    if (t < T_DIM) {
        #pragma unroll
        for (int j = 0; j < 4; ++j) {
            const int c = cBase + ty + j * 8;
            outp[c * T_DIM + t] = tile[tx][ty + j * 8];
        }
    }
}

// Index tails. nt = 5: channel_indices[i] = i/5, time_indices[i] = i%5, i in [0,320).
__global__ void labram_indices_f32_kernel(float* __restrict__ out)
{
    const int i = blockIdx.x * blockDim.x + threadIdx.x;
    if (i < 320) {
        out[PATCH_ELEMS + i]        = (float)(i / 5);
        out[PATCH_ELEMS + 320 + i]  = (float)(i % 5);
    }
}

__global__ void labram_indices_i64_kernel(long long* __restrict__ tail)
{
    const int i = blockIdx.x * blockDim.x + threadIdx.x;
    if (i < 320) {
        tail[i]        = (long long)(i / 5);
        tail[320 + i]  = (long long)(i % 5);
    }
}

extern "C" void kernel_launch(void* const* d_in, const int* in_sizes, int n_in,
                              void* d_out, int out_size)
{
    const float* eeg = (const float*)d_in[0];
    float* out = (float*)d_out;

    dim3 block(32, 8);
    dim3 grid(C_DIM / TILE,                 // 2 channel tiles
              (T_DIM + TILE - 1) / TILE,    // 32 time tiles
              N_BW);                        // 512 batches
    labram_transpose_kernel<<<grid, block>>>(eeg, out);

    const long long tail = (long long)out_size - (long long)PATCH_ELEMS;
    if (tail == 640) {
        // indices stored as float32, 320 + 320
        labram_indices_f32_kernel<<<2, 256>>>(out);
    } else if (tail == 1280) {
        // indices stored as raw int64 (each occupies two f32 slots)
        long long* t64 = (long long*)(out + PATCH_ELEMS);
        labram_indices_i64_kernel<<<2, 256>>>(t64);
    } else if (tail >= 640) {
        // unknown layout with room: default to float32 encoding
        labram_indices_f32_kernel<<<2, 256>>>(out);
    }
    // tail == 0: patches-only output, nothing else to write
}

// round 3
// speedup vs baseline: 1.1506x; 1.1506x over previous
#include <cuda_runtime.h>
#include <cuda_bf16.h>
#include <cstdint>

// eeg_input [16, 32, 1000, 64] fp32 -> per (b,w) slab: 64x1000 transpose of 1000x64.
//   out[bw][c*1000 + t] = in[bw][t*64 + c]
// Tail (out_size - PATCH_ELEMS == 640, f32): channel = i/5, time = i%5, i in [0,320).

#define N_BW   512
#define T_DIM  1000
#define C_DIM  64
#define PATCH_ELEMS (N_BW * T_DIM * C_DIM)   // 32,768,000 floats

// Tile: 32 channels x 128 time steps per CTA, 256 threads.
// smem padded to 33 floats per t-row -> both scalar smem phases conflict-free.
__global__ __launch_bounds__(256) void labram_transpose_fused_kernel(
    const float* __restrict__ in, float* __restrict__ out, int tail_mode)
{
    __shared__ float tile[128][33];

    const int bw    = blockIdx.z;
    const int tBase = blockIdx.y * 128;
    const int cBase = blockIdx.x * 32;

    const float* __restrict__ inp  = in  + (size_t)bw * (T_DIM * C_DIM);
    float*       __restrict__ outp = out + (size_t)bw * (T_DIM * C_DIM);

    const int tid = threadIdx.x;

    // ---- Load phase: float4 along c, 4 independent front-batched LDG.128 ----
    const int cq = tid & 7;    // float4 column within 32-c tile (0..7)
    const int tr = tid >> 3;   // local t row (0..31), rounds add +32

    float4 v[4];
    bool   p[4];
    #pragma unroll
    for (int j = 0; j < 4; ++j) {
        const int t = tBase + tr + 32 * j;
        p[j] = (t < T_DIM);
        if (p[j]) {
            v[j] = *reinterpret_cast<const float4*>(inp + t * C_DIM + cBase + 4 * cq);
        }
    }
    #pragma unroll
    for (int j = 0; j < 4; ++j) {
        if (p[j]) {
            const int lt = tr + 32 * j;
            tile[lt][4 * cq + 0] = v[j].x;
            tile[lt][4 * cq + 1] = v[j].y;
            tile[lt][4 * cq + 2] = v[j].z;
            tile[lt][4 * cq + 3] = v[j].w;
        }
    }
    __syncthreads();

    // ---- Store phase: float4 along t, STG.128 ----
    const int c  = tid >> 3;   // local channel (0..31)
    const int tq = tid & 7;    // t-quad index within round

    #pragma unroll
    for (int r = 0; r < 4; ++r) {
        const int ltb = 4 * (tq + 8 * r);    // local t base (0..124, step 4)
        const int t   = tBase + ltb;
        if (t + 3 < T_DIM) {
            float4 o;
            o.x = tile[ltb + 0][c];
            o.y = tile[ltb + 1][c];
            o.z = tile[ltb + 2][c];
            o.w = tile[ltb + 3][c];
            *reinterpret_cast<float4*>(outp + (cBase + c) * T_DIM + t) = o;
        }
    }

    // ---- Fused index tail (one CTA only) ----
    if (tail_mode != 0 && blockIdx.x == 0 && blockIdx.y == 0 && blockIdx.z == 0) {
        for (int i = tid; i < 320; i += 256) {
            if (tail_mode == 1) {            // float32-encoded indices
                out[PATCH_ELEMS + i]       = (float)(i / 5);
                out[PATCH_ELEMS + 320 + i] = (float)(i % 5);
            } else {                          // raw int64 indices
                long long* t64 = (long long*)(out + PATCH_ELEMS);
                t64[i]       = (long long)(i / 5);
                t64[320 + i] = (long long)(i % 5);
            }
        }
    }
}

extern "C" void kernel_launch(void* const* d_in, const int* in_sizes, int n_in,
                              void* d_out, int out_size)
{
    const float* eeg = (const float*)d_in[0];
    float* out = (float*)d_out;

    const long long tail = (long long)out_size - (long long)PATCH_ELEMS;
    int tail_mode = 0;
    if (tail == 1280)     tail_mode = 2;   // int64 tail
    else if (tail >= 640) tail_mode = 1;   // float32 tail (observed case)

    dim3 block(256);
    dim3 grid(C_DIM / 32,                    // 2 channel tiles
              (T_DIM + 127) / 128,           // 8 time tiles (last partial: 104)
              N_BW);                         // 512 batches
    labram_transpose_fused_kernel<<<grid, block>>>(eeg, out, tail_mode);
}